// round 2
// baseline (speedup 1.0000x reference)
#include <cuda_runtime.h>

#define HH 256
#define WW 512
#define CC 32
#define BB 2
#define HL (HH/4)
#define WL (WW/4)

// Tile: 32 wide x 8 tall pixels per CTA, 256 threads, 1 thread = 1 pixel.
// LR blocks covered: 8 wide x 2 tall; lr neighborhood needed: 10 x 4 blocks.
__global__ void __launch_bounds__(256, 2)
erc_kernel(const float* __restrict__ lr, const float* __restrict__ hr,
           const float* __restrict__ w0, const float* __restrict__ w1,
           const float* __restrict__ w2, const float* __restrict__ w3,
           float* __restrict__ out)
{
    __shared__ __align__(16) float s_w0T[66*32];     // [k][o]  (w0 transposed)
    __shared__ __align__(16) float s_w1[16*32];      // [o][k]
    __shared__ __align__(16) float s_w2[8*16];       // [o][k]
    __shared__ __align__(16) float s_w3[8];
    __shared__ __align__(16) float s_bias[144*36];   // [par*9+d][o] pad->36: conflict-free
    __shared__ __align__(16) float s_lrvec[40*32];   // [j*10+i][c]  lr vectors (clamped nbhd)
    __shared__ __align__(16) float s_lrproj[40*36];  // [j*10+i][o]  W0_lr @ lrvec, pad->36

    const int tid = threadIdx.x;
    const int b  = blockIdx.z;
    const int tx = tid & 31, ty = tid >> 5;
    const int h = blockIdx.y * 8 + ty;
    const int w = blockIdx.x * 32 + tx;

    // ---------------- Phase A: stage weights + lr vectors ----------------
    for (int idx = tid; idx < 66*32; idx += 256) {
        int k = idx >> 5, o = idx & 31;
        s_w0T[idx] = w0[o*66 + k];
    }
    for (int idx = tid; idx < 16*32; idx += 256) s_w1[idx] = w1[idx];
    if (tid < 8*16) s_w2[tid] = w2[tid];
    if (tid < 8)    s_w3[tid] = w3[tid];
    {
        const int y0 = blockIdx.y * 2 - 1;
        const int x0 = blockIdx.x * 8 - 1;
        for (int idx = tid; idx < 40*32; idx += 256) {
            int c = idx & 31, pos = idx >> 5;
            int j = pos / 10, i = pos - j*10;
            int yy = min(max(y0 + j, 0), HL - 1);   // clamped loads are only
            int xx = min(max(x0 + i, 0), WL - 1);   // consumed by masked dirs
            s_lrvec[idx] = lr[(((size_t)b*CC + c)*HL + yy)*WL + xx];
        }
    }
    __syncthreads();

    // ------- Phase B: bias table (distance part) + lr projections -------
    // direction order: c, l, r, t, b, lt, rt, lb, rb
    // dA code per dir (width ch):  0=x[px], 1=4-px, 2=px+1
    // dB code per dir (height ch): 0=x[py], 1=4-py, 2=py+1
    for (int idx = tid; idx < 16*9*32; idx += 256) {
        int o = idx & 31;
        int r = idx >> 5;
        int d = r % 9, par = r / 9;
        int py = par >> 2, px = par & 3;
        const unsigned CA = (0u<<0)|(1u<<2)|(2u<<4)|(0u<<6)|(0u<<8)|(1u<<10)|(2u<<12)|(0u<<14)|(0u<<16);
        const unsigned CB = (0u<<0)|(0u<<2)|(0u<<4)|(1u<<6)|(2u<<8)|(0u<<10)|(0u<<12)|(1u<<14)|(2u<<16);
        int ca = (CA >> (2*d)) & 3, cb = (CB >> (2*d)) & 3;
        float dA = (ca == 0) ? (float)((px < 2) ? px - 2 : px - 1)
                 : (ca == 1) ? (float)(4 - px) : (float)(px + 1);
        float dB = (cb == 0) ? (float)((py < 2) ? py - 2 : py - 1)
                 : (cb == 1) ? (float)(4 - py) : (float)(py + 1);
        s_bias[r*36 + o] = dA * s_w0T[64*32 + o] + dB * s_w0T[65*32 + o];
    }
    for (int idx = tid; idx < 40*32; idx += 256) {
        int o = idx & 31, pos = idx >> 5;
        const float4* v4 = (const float4*)&s_lrvec[pos*32];
        float acc = 0.f;
#pragma unroll
        for (int c4 = 0; c4 < 8; ++c4) {
            float4 v = v4[c4];
            acc = fmaf(v.x, s_w0T[(c4*4+0)*32 + o], acc);
            acc = fmaf(v.y, s_w0T[(c4*4+1)*32 + o], acc);
            acc = fmaf(v.z, s_w0T[(c4*4+2)*32 + o], acc);
            acc = fmaf(v.w, s_w0T[(c4*4+3)*32 + o], acc);
        }
        s_lrproj[pos*36 + o] = acc;
    }
    __syncthreads();

    // ---------------- Phase C: per-pixel MLP, 9 directions ----------------
    // hrproj = W0_hr @ hr  (shared by all 9 directions) — streamed loads, no hv[] array
    float hrp[32];
#pragma unroll
    for (int o = 0; o < 32; ++o) hrp[o] = 0.f;
    {
        const float* p = hr + (size_t)b*CC*HH*WW + (size_t)h*WW + w;
        float va0 = p[0*(size_t)HH*WW], va1 = p[1*(size_t)HH*WW],
              va2 = p[2*(size_t)HH*WW], va3 = p[3*(size_t)HH*WW];
#pragma unroll
        for (int t = 0; t < 8; ++t) {
            float vb0, vb1, vb2, vb3;
            if (t < 7) {
                vb0 = p[(size_t)(t*4+4)*HH*WW];
                vb1 = p[(size_t)(t*4+5)*HH*WW];
                vb2 = p[(size_t)(t*4+6)*HH*WW];
                vb3 = p[(size_t)(t*4+7)*HH*WW];
            }
            float vv[4] = {va0, va1, va2, va3};
#pragma unroll
            for (int j = 0; j < 4; ++j) {
                const float v = vv[j];
                const float4* wr = (const float4*)&s_w0T[(32 + t*4 + j)*32];
#pragma unroll
                for (int o4 = 0; o4 < 8; ++o4) {
                    float4 ww = wr[o4];
                    hrp[o4*4+0] = fmaf(v, ww.x, hrp[o4*4+0]);
                    hrp[o4*4+1] = fmaf(v, ww.y, hrp[o4*4+1]);
                    hrp[o4*4+2] = fmaf(v, ww.z, hrp[o4*4+2]);
                    hrp[o4*4+3] = fmaf(v, ww.w, hrp[o4*4+3]);
                }
            }
            if (t < 7) { va0 = vb0; va1 = vb1; va2 = vb2; va3 = vb3; }
        }
    }

    const int par = ((h & 3) << 2) | (w & 3);
    const int byl = ty >> 2, bxl = tx >> 2;
    // packed (dy+1), (dx+1) per direction
    const unsigned DY1 = (1u<<0)|(1u<<2)|(1u<<4)|(0u<<6)|(2u<<8)|(0u<<10)|(0u<<12)|(2u<<14)|(2u<<16);
    const unsigned DX1 = (1u<<0)|(0u<<2)|(2u<<4)|(1u<<6)|(1u<<8)|(0u<<10)|(2u<<12)|(0u<<14)|(2u<<16);

    float lv[9];

#pragma unroll 1
    for (int d = 0; d < 9; ++d) {
        const int dy1 = (DY1 >> (2*d)) & 3;
        const int dx1 = (DX1 >> (2*d)) & 3;
        bool valid = true;
        if (dx1 == 0) valid = valid && (w >= 4);
        if (dx1 == 2) valid = valid && (w < WW - 4);
        if (dy1 == 0) valid = valid && (h >= 4);
        if (dy1 == 2) valid = valid && (h < HH - 4);

        const float4* lp = (const float4*)&s_lrproj[((byl + dy1)*10 + (bxl + dx1))*36];
        const float4* bp = (const float4*)&s_bias[(par*9 + d)*36];

        // layer1 accumulated over 4 k-tiles of 8 (keeps live set small)
        float h1[16];
#pragma unroll
        for (int o = 0; o < 16; ++o) h1[o] = 0.f;
#pragma unroll
        for (int t = 0; t < 4; ++t) {
            float4 l0 = lp[t*2+0], l1 = lp[t*2+1];
            float4 b0 = bp[t*2+0], b1 = bp[t*2+1];
            float h0t[8];
            float v;
            v = hrp[t*8+0] + l0.x + b0.x; h0t[0] = fmaxf(v, 0.01f*v);
            v = hrp[t*8+1] + l0.y + b0.y; h0t[1] = fmaxf(v, 0.01f*v);
            v = hrp[t*8+2] + l0.z + b0.z; h0t[2] = fmaxf(v, 0.01f*v);
            v = hrp[t*8+3] + l0.w + b0.w; h0t[3] = fmaxf(v, 0.01f*v);
            v = hrp[t*8+4] + l1.x + b1.x; h0t[4] = fmaxf(v, 0.01f*v);
            v = hrp[t*8+5] + l1.y + b1.y; h0t[5] = fmaxf(v, 0.01f*v);
            v = hrp[t*8+6] + l1.z + b1.z; h0t[6] = fmaxf(v, 0.01f*v);
            v = hrp[t*8+7] + l1.w + b1.w; h0t[7] = fmaxf(v, 0.01f*v);
#pragma unroll
            for (int o = 0; o < 16; ++o) {
                const float4* wr = (const float4*)&s_w1[o*32 + t*8];
                float4 wa = wr[0], wb = wr[1];
                float a = h1[o];
                a = fmaf(wa.x, h0t[0], a);
                a = fmaf(wa.y, h0t[1], a);
                a = fmaf(wa.z, h0t[2], a);
                a = fmaf(wa.w, h0t[3], a);
                a = fmaf(wb.x, h0t[4], a);
                a = fmaf(wb.y, h0t[5], a);
                a = fmaf(wb.z, h0t[6], a);
                a = fmaf(wb.w, h0t[7], a);
                h1[o] = a;
            }
        }
#pragma unroll
        for (int o = 0; o < 16; ++o) h1[o] = fmaxf(h1[o], 0.01f*h1[o]);

        float h2[8];
#pragma unroll
        for (int o = 0; o < 8; ++o) {
            const float4* wr = (const float4*)&s_w2[o*16];
            float a = 0.f;
#pragma unroll
            for (int k4 = 0; k4 < 4; ++k4) {
                float4 ww = wr[k4];
                a = fmaf(ww.x, h1[k4*4+0], a);
                a = fmaf(ww.y, h1[k4*4+1], a);
                a = fmaf(ww.z, h1[k4*4+2], a);
                a = fmaf(ww.w, h1[k4*4+3], a);
            }
            h2[o] = fmaxf(a, 0.01f*a);
        }
        float a = 0.f;
        {
            const float4* wr = (const float4*)s_w3;
            float4 wa = wr[0], wb = wr[1];
            a = fmaf(wa.x, h2[0], a);
            a = fmaf(wa.y, h2[1], a);
            a = fmaf(wa.z, h2[2], a);
            a = fmaf(wa.w, h2[3], a);
            a = fmaf(wb.x, h2[4], a);
            a = fmaf(wb.y, h2[5], a);
            a = fmaf(wb.z, h2[6], a);
            a = fmaf(wb.w, h2[7], a);
        }
        lv[d] = valid ? a : -100.0f;
    }

    // ---------------- softmax over the 9 directions ----------------
    float m = lv[0];
#pragma unroll
    for (int d = 1; d < 9; ++d) m = fmaxf(m, lv[d]);
    float ssum = 0.f;
#pragma unroll
    for (int d = 0; d < 9; ++d) { float e = __expf(lv[d] - m); ssum += e; lv[d] = e; }
    const float inv = 1.0f / ssum;
    float* op = out + (size_t)b*9*HH*WW + (size_t)h*WW + w;
#pragma unroll
    for (int d = 0; d < 9; ++d) op[(size_t)d*HH*WW] = lv[d] * inv;
}

extern "C" void kernel_launch(void* const* d_in, const int* in_sizes, int n_in,
                              void* d_out, int out_size) {
    const float* lr = (const float*)d_in[0];
    const float* hr = (const float*)d_in[1];
    // d_in[2], d_in[3] (lr_feature_r / hr_feature_r) are unused by the reference.
    const float* w0 = (const float*)d_in[4];
    const float* w1 = (const float*)d_in[5];
    const float* w2 = (const float*)d_in[6];
    const float* w3 = (const float*)d_in[7];
    dim3 grid(WW/32, HH/8, BB);
    erc_kernel<<<grid, 256>>>(lr, hr, w0, w1, w2, w3, (float*)d_out);
}

// round 3
// speedup vs baseline: 9.3249x; 9.3249x over previous
#include <cuda_runtime.h>

#define HH 256
#define WW 512
#define CC 32
#define BB 2
#define HL (HH/4)
#define WL (WW/4)

// Tile: 32 wide x 8 tall pixels per CTA, 256 threads, 1 thread = 1 pixel.
// LR blocks covered: 8 wide x 2 tall; lr neighborhood needed: 10 x 4 blocks.
// launch_bounds(256,1): full 255-reg budget -> no spills (round-1/2 lesson).
__global__ void __launch_bounds__(256, 1)
erc_kernel(const float* __restrict__ lr, const float* __restrict__ hr,
           const float* __restrict__ w0, const float* __restrict__ w1,
           const float* __restrict__ w2, const float* __restrict__ w3,
           float* __restrict__ out)
{
    __shared__ __align__(16) float s_w0T[66*32];     // [k][o]  (w0 transposed)
    __shared__ __align__(16) float s_w1[16*32];      // [o][k]
    __shared__ __align__(16) float s_w2[8*16];       // [o][k]
    __shared__ __align__(16) float s_w3[8];
    __shared__ __align__(16) float s_lrvec[40*32];   // [j*10+i][c]  lr vectors (clamped nbhd)
    __shared__ __align__(16) float s_lrproj[40*36];  // [j*10+i][o]  W0_lr @ lrvec, pad->36
    __shared__ float s_logit[256*9];                 // [tid*9+d], stride 9: conflict-free

    const int tid = threadIdx.x;
    const int b  = blockIdx.z;
    const int tx = tid & 31, ty = tid >> 5;
    const int h = blockIdx.y * 8 + ty;
    const int w = blockIdx.x * 32 + tx;

    // ---------------- Phase A: stage weights + lr vectors ----------------
    for (int idx = tid; idx < 66*32; idx += 256) {
        int k = idx >> 5, o = idx & 31;
        s_w0T[idx] = w0[o*66 + k];
    }
    for (int idx = tid; idx < 16*32; idx += 256) s_w1[idx] = w1[idx];
    if (tid < 8*16) s_w2[tid] = w2[tid];
    if (tid < 8)    s_w3[tid] = w3[tid];
    {
        const int y0 = blockIdx.y * 2 - 1;
        const int x0 = blockIdx.x * 8 - 1;
        for (int idx = tid; idx < 40*32; idx += 256) {
            int c = idx & 31, pos = idx >> 5;
            int j = pos / 10, i = pos - j*10;
            int yy = min(max(y0 + j, 0), HL - 1);   // clamped loads are only
            int xx = min(max(x0 + i, 0), WL - 1);   // consumed by masked dirs
            s_lrvec[idx] = lr[(((size_t)b*CC + c)*HL + yy)*WL + xx];
        }
    }
    __syncthreads();

    // ------- Phase B: lr projections (W0_lr @ lrvec) -------
    for (int idx = tid; idx < 40*32; idx += 256) {
        int o = idx & 31, pos = idx >> 5;
        const float4* v4 = (const float4*)&s_lrvec[pos*32];
        float acc = 0.f;
#pragma unroll
        for (int c4 = 0; c4 < 8; ++c4) {
            float4 v = v4[c4];
            acc = fmaf(v.x, s_w0T[(c4*4+0)*32 + o], acc);
            acc = fmaf(v.y, s_w0T[(c4*4+1)*32 + o], acc);
            acc = fmaf(v.z, s_w0T[(c4*4+2)*32 + o], acc);
            acc = fmaf(v.w, s_w0T[(c4*4+3)*32 + o], acc);
        }
        s_lrproj[pos*36 + o] = acc;
    }
    __syncthreads();

    // ---------------- Phase C: per-pixel MLP, 9 directions ----------------
    // hrproj = W0_hr @ hr  (shared by all 9 directions)
    float hrp[32];
#pragma unroll
    for (int o = 0; o < 32; ++o) hrp[o] = 0.f;
    {
        const float* p = hr + (size_t)b*CC*HH*WW + (size_t)h*WW + w;
        float hv[32];
#pragma unroll
        for (int c = 0; c < 32; ++c) hv[c] = p[(size_t)c*HH*WW];
#pragma unroll
        for (int c = 0; c < 32; ++c) {
            const float v = hv[c];
            const float4* wr = (const float4*)&s_w0T[(32 + c)*32];
#pragma unroll
            for (int o4 = 0; o4 < 8; ++o4) {
                float4 ww = wr[o4];
                hrp[o4*4+0] = fmaf(v, ww.x, hrp[o4*4+0]);
                hrp[o4*4+1] = fmaf(v, ww.y, hrp[o4*4+1]);
                hrp[o4*4+2] = fmaf(v, ww.z, hrp[o4*4+2]);
                hrp[o4*4+3] = fmaf(v, ww.w, hrp[o4*4+3]);
            }
        }
    }

    const int px = w & 3, py = h & 3;
    const int byl = ty >> 2, bxl = tx >> 2;
    // distance scalars: code 0 = x-value [-2,-1,1,2], 1 = 4-p, 2 = p+1
    const float fxa0 = (float)((px < 2) ? px - 2 : px - 1);
    const float fxa1 = (float)(4 - px);
    const float fxa2 = (float)(px + 1);
    const float fyb0 = (float)((py < 2) ? py - 2 : py - 1);
    const float fyb1 = (float)(4 - py);
    const float fyb2 = (float)(py + 1);
    // direction order: c, l, r, t, b, lt, rt, lb, rb
    const unsigned CA = (0u<<0)|(1u<<2)|(2u<<4)|(0u<<6)|(0u<<8)|(1u<<10)|(2u<<12)|(0u<<14)|(0u<<16);
    const unsigned CB = (0u<<0)|(0u<<2)|(0u<<4)|(1u<<6)|(2u<<8)|(0u<<10)|(0u<<12)|(1u<<14)|(2u<<16);
    // packed (dy+1), (dx+1) per direction
    const unsigned DY1 = (1u<<0)|(1u<<2)|(1u<<4)|(0u<<6)|(2u<<8)|(0u<<10)|(0u<<12)|(2u<<14)|(2u<<16);
    const unsigned DX1 = (1u<<0)|(0u<<2)|(2u<<4)|(1u<<6)|(1u<<8)|(0u<<10)|(2u<<12)|(0u<<14)|(2u<<16);

#pragma unroll 1
    for (int d = 0; d < 9; ++d) {
        const int dy1 = (DY1 >> (2*d)) & 3;
        const int dx1 = (DX1 >> (2*d)) & 3;
        bool valid = true;
        if (dx1 == 0) valid = valid && (w >= 4);
        if (dx1 == 2) valid = valid && (w < WW - 4);
        if (dy1 == 0) valid = valid && (h >= 4);
        if (dy1 == 2) valid = valid && (h < HH - 4);

        const int ca = (CA >> (2*d)) & 3, cb = (CB >> (2*d)) & 3;
        const float dA = (ca == 0) ? fxa0 : ((ca == 1) ? fxa1 : fxa2);
        const float dB = (cb == 0) ? fyb0 : ((cb == 1) ? fyb1 : fyb2);

        const float4* lp = (const float4*)&s_lrproj[((byl + dy1)*10 + (bxl + dx1))*36];
        const float4* wa = (const float4*)&s_w0T[64*32];
        const float4* wb = (const float4*)&s_w0T[65*32];

        // layer1 accumulated over 4 k-tiles of 8 (keeps live set small)
        float h1[16];
#pragma unroll
        for (int o = 0; o < 16; ++o) h1[o] = 0.f;
#pragma unroll
        for (int t = 0; t < 4; ++t) {
            float4 l0 = lp[t*2+0], l1 = lp[t*2+1];
            float4 a0 = wa[t*2+0], a1 = wa[t*2+1];
            float4 b0 = wb[t*2+0], b1 = wb[t*2+1];
            float h0t[8];
            float v;
            v = fmaf(dA, a0.x, hrp[t*8+0] + l0.x); v = fmaf(dB, b0.x, v); h0t[0] = fmaxf(v, 0.01f*v);
            v = fmaf(dA, a0.y, hrp[t*8+1] + l0.y); v = fmaf(dB, b0.y, v); h0t[1] = fmaxf(v, 0.01f*v);
            v = fmaf(dA, a0.z, hrp[t*8+2] + l0.z); v = fmaf(dB, b0.z, v); h0t[2] = fmaxf(v, 0.01f*v);
            v = fmaf(dA, a0.w, hrp[t*8+3] + l0.w); v = fmaf(dB, b0.w, v); h0t[3] = fmaxf(v, 0.01f*v);
            v = fmaf(dA, a1.x, hrp[t*8+4] + l1.x); v = fmaf(dB, b1.x, v); h0t[4] = fmaxf(v, 0.01f*v);
            v = fmaf(dA, a1.y, hrp[t*8+5] + l1.y); v = fmaf(dB, b1.y, v); h0t[5] = fmaxf(v, 0.01f*v);
            v = fmaf(dA, a1.z, hrp[t*8+6] + l1.z); v = fmaf(dB, b1.z, v); h0t[6] = fmaxf(v, 0.01f*v);
            v = fmaf(dA, a1.w, hrp[t*8+7] + l1.w); v = fmaf(dB, b1.w, v); h0t[7] = fmaxf(v, 0.01f*v);
#pragma unroll
            for (int o = 0; o < 16; ++o) {
                const float4* wr = (const float4*)&s_w1[o*32 + t*8];
                float4 wx = wr[0], wy = wr[1];
                float a = h1[o];
                a = fmaf(wx.x, h0t[0], a);
                a = fmaf(wx.y, h0t[1], a);
                a = fmaf(wx.z, h0t[2], a);
                a = fmaf(wx.w, h0t[3], a);
                a = fmaf(wy.x, h0t[4], a);
                a = fmaf(wy.y, h0t[5], a);
                a = fmaf(wy.z, h0t[6], a);
                a = fmaf(wy.w, h0t[7], a);
                h1[o] = a;
            }
        }
#pragma unroll
        for (int o = 0; o < 16; ++o) h1[o] = fmaxf(h1[o], 0.01f*h1[o]);

        float h2[8];
#pragma unroll
        for (int o = 0; o < 8; ++o) {
            const float4* wr = (const float4*)&s_w2[o*16];
            float a = 0.f;
#pragma unroll
            for (int k4 = 0; k4 < 4; ++k4) {
                float4 ww = wr[k4];
                a = fmaf(ww.x, h1[k4*4+0], a);
                a = fmaf(ww.y, h1[k4*4+1], a);
                a = fmaf(ww.z, h1[k4*4+2], a);
                a = fmaf(ww.w, h1[k4*4+3], a);
            }
            h2[o] = fmaxf(a, 0.01f*a);
        }
        float a = 0.f;
        {
            const float4* wr = (const float4*)s_w3;
            float4 wx = wr[0], wy = wr[1];
            a = fmaf(wx.x, h2[0], a);
            a = fmaf(wx.y, h2[1], a);
            a = fmaf(wx.z, h2[2], a);
            a = fmaf(wx.w, h2[3], a);
            a = fmaf(wy.x, h2[4], a);
            a = fmaf(wy.y, h2[5], a);
            a = fmaf(wy.z, h2[6], a);
            a = fmaf(wy.w, h2[7], a);
        }
        s_logit[tid*9 + d] = valid ? a : -100.0f;
    }

    // ---------------- softmax over the 9 directions ----------------
    float lv[9];
#pragma unroll
    for (int d = 0; d < 9; ++d) lv[d] = s_logit[tid*9 + d];
    float m = lv[0];
#pragma unroll
    for (int d = 1; d < 9; ++d) m = fmaxf(m, lv[d]);
    float ssum = 0.f;
#pragma unroll
    for (int d = 0; d < 9; ++d) { float e = __expf(lv[d] - m); ssum += e; lv[d] = e; }
    const float inv = 1.0f / ssum;
    float* op = out + (size_t)b*9*HH*WW + (size_t)h*WW + w;
#pragma unroll
    for (int d = 0; d < 9; ++d) op[(size_t)d*HH*WW] = lv[d] * inv;
}

extern "C" void kernel_launch(void* const* d_in, const int* in_sizes, int n_in,
                              void* d_out, int out_size) {
    const float* lr = (const float*)d_in[0];
    const float* hr = (const float*)d_in[1];
    // d_in[2], d_in[3] (lr_feature_r / hr_feature_r) are unused by the reference.
    const float* w0 = (const float*)d_in[4];
    const float* w1 = (const float*)d_in[5];
    const float* w2 = (const float*)d_in[6];
    const float* w3 = (const float*)d_in[7];
    dim3 grid(WW/32, HH/8, BB);
    erc_kernel<<<grid, 256>>>(lr, hr, w0, w1, w2, w3, (float*)d_out);
}

// round 4
// speedup vs baseline: 10.9140x; 1.1704x over previous
#include <cuda_runtime.h>

#define HH 256
#define WW 512
#define CC 32
#define BB 2
#define HL (HH/4)
#define WL (WW/4)
#define HWs ((size_t)HH*WW)

typedef unsigned long long u64;

#define FMA2(d,a,b,c) asm("fma.rn.f32x2 %0,%1,%2,%3;" : "=l"(d) : "l"(a), "l"(b), "l"(c))
#define ADD2(d,a,b)   asm("add.rn.f32x2 %0,%1,%2;"    : "=l"(d) : "l"(a), "l"(b))
#define PACK2(d,lo,hi) asm("mov.b64 %0,{%1,%2};" : "=l"(d) : "r"(__float_as_uint(lo)), "r"(__float_as_uint(hi)))
#define UNPK2(lo,hi,s) do { unsigned _ul,_uh; \
    asm("mov.b64 {%0,%1},%2;" : "=r"(_ul), "=r"(_uh) : "l"(s)); \
    (lo)=__uint_as_float(_ul); (hi)=__uint_as_float(_uh); } while(0)

// Tile: 64 wide x 8 tall. 256 threads; thread owns pixels (h,w) and (h,w+32).
// LR blocks: 16 wide x 2 tall; neighborhood 18 x 4.
__global__ void __launch_bounds__(256, 1)
erc_kernel(const float* __restrict__ lr, const float* __restrict__ hr,
           const float* __restrict__ w0, const float* __restrict__ w1,
           const float* __restrict__ w2, const float* __restrict__ w3,
           float* __restrict__ out)
{
    __shared__ __align__(16) float s_w0T[66*32];     // [k][o]
    __shared__ __align__(16) float s_w1T[32*16];     // [k][o]  (transposed for o-pairs)
    __shared__ __align__(16) float s_w2T[16*8];      // [k][o]
    __shared__ __align__(16) float s_w3[8];
    __shared__ __align__(16) float s_lrvec[72*32];   // [j*18+i][c]
    __shared__ __align__(16) float s_lrproj[72*36];  // [j*18+i][o], pad->36
    __shared__ float s_logit[512*9];                 // [pix*9+d]

    const int tid = threadIdx.x;
    const int b  = blockIdx.z;
    const int tx = tid & 31, ty = tid >> 5;
    const int h  = blockIdx.y * 8 + ty;
    const int wA = blockIdx.x * 64 + tx;
    const int wB = wA + 32;

    // ---------------- Phase A: stage weights + lr vectors ----------------
    for (int idx = tid; idx < 66*32; idx += 256) {
        int k = idx >> 5, o = idx & 31;
        s_w0T[idx] = w0[o*66 + k];
    }
    for (int idx = tid; idx < 32*16; idx += 256) {
        int k = idx >> 4, o = idx & 15;
        s_w1T[idx] = w1[o*32 + k];
    }
    if (tid < 16*8) { int k = tid >> 3, o = tid & 7; s_w2T[tid] = w2[o*16 + k]; }
    if (tid < 8)    s_w3[tid] = w3[tid];
    {
        const int y0 = blockIdx.y * 2 - 1;
        const int x0 = blockIdx.x * 16 - 1;
        for (int idx = tid; idx < 72*32; idx += 256) {
            int c = idx & 31, pos = idx >> 5;
            int j = pos / 18, i = pos - j*18;
            int yy = min(max(y0 + j, 0), HL - 1);   // clamped loads only feed masked dirs
            int xx = min(max(x0 + i, 0), WL - 1);
            s_lrvec[idx] = lr[(((size_t)b*CC + c)*HL + yy)*WL + xx];
        }
    }
    __syncthreads();

    // ------- Phase B: lr projections (W0_lr @ lrvec) -------
    for (int idx = tid; idx < 72*32; idx += 256) {
        int o = idx & 31, pos = idx >> 5;
        const float4* v4 = (const float4*)&s_lrvec[pos*32];
        float acc = 0.f;
#pragma unroll
        for (int c4 = 0; c4 < 8; ++c4) {
            float4 v = v4[c4];
            acc = fmaf(v.x, s_w0T[(c4*4+0)*32 + o], acc);
            acc = fmaf(v.y, s_w0T[(c4*4+1)*32 + o], acc);
            acc = fmaf(v.z, s_w0T[(c4*4+2)*32 + o], acc);
            acc = fmaf(v.w, s_w0T[(c4*4+3)*32 + o], acc);
        }
        s_lrproj[pos*36 + o] = acc;
    }
    __syncthreads();

    // ---------------- Phase C: hrproj (packed o-pairs, both pixels) ----------------
    u64 hrpA[16], hrpB[16];
#pragma unroll
    for (int j = 0; j < 16; ++j) { hrpA[j] = 0ull; hrpB[j] = 0ull; }
    {
        const float* p = hr + (size_t)b*CC*HWs + (size_t)h*WW + wA;
#pragma unroll
        for (int ct = 0; ct < 4; ++ct) {
            float fA[8], fB[8];
#pragma unroll
            for (int j = 0; j < 8; ++j) {
                fA[j] = p[(size_t)(ct*8+j)*HWs];
                fB[j] = p[(size_t)(ct*8+j)*HWs + 32];
            }
#pragma unroll
            for (int j = 0; j < 8; ++j) {
                u64 vA2, vB2;
                PACK2(vA2, fA[j], fA[j]);
                PACK2(vB2, fB[j], fB[j]);
                const ulonglong2* wr = (const ulonglong2*)&s_w0T[(32 + ct*8 + j)*32];
#pragma unroll
                for (int q = 0; q < 8; ++q) {
                    ulonglong2 ww = wr[q];
                    FMA2(hrpA[q*2+0], ww.x, vA2, hrpA[q*2+0]);
                    FMA2(hrpA[q*2+1], ww.y, vA2, hrpA[q*2+1]);
                    FMA2(hrpB[q*2+0], ww.x, vB2, hrpB[q*2+0]);
                    FMA2(hrpB[q*2+1], ww.y, vB2, hrpB[q*2+1]);
                }
            }
        }
    }

    const int px = wA & 3, py = h & 3;   // wB has same parity (32 % 4 == 0)
    const int byl = ty >> 2;
    const int bxlA = tx >> 2;
    // distance scalars: code 0 = x-value [-2,-1,1,2], 1 = 4-p, 2 = p+1
    const float fxa0 = (float)((px < 2) ? px - 2 : px - 1);
    const float fxa1 = (float)(4 - px);
    const float fxa2 = (float)(px + 1);
    const float fyb0 = (float)((py < 2) ? py - 2 : py - 1);
    const float fyb1 = (float)(4 - py);
    const float fyb2 = (float)(py + 1);
    // direction order: c, l, r, t, b, lt, rt, lb, rb
    const unsigned CA  = (0u<<0)|(1u<<2)|(2u<<4)|(0u<<6)|(0u<<8)|(1u<<10)|(2u<<12)|(0u<<14)|(0u<<16);
    const unsigned CB  = (0u<<0)|(0u<<2)|(0u<<4)|(1u<<6)|(2u<<8)|(0u<<10)|(0u<<12)|(1u<<14)|(2u<<16);
    const unsigned DY1 = (1u<<0)|(1u<<2)|(1u<<4)|(0u<<6)|(2u<<8)|(0u<<10)|(0u<<12)|(2u<<14)|(2u<<16);
    const unsigned DX1 = (1u<<0)|(0u<<2)|(2u<<4)|(1u<<6)|(1u<<8)|(0u<<10)|(2u<<12)|(0u<<14)|(2u<<16);

    float w3r[8];
#pragma unroll
    for (int j = 0; j < 8; ++j) w3r[j] = s_w3[j];

#pragma unroll 1
    for (int d = 0; d < 9; ++d) {
        const int dy1 = (DY1 >> (2*d)) & 3;
        const int dx1 = (DX1 >> (2*d)) & 3;
        bool validA = true, validB = true;
        if (dx1 == 0) { validA = validA && (wA >= 4);     validB = validB && (wB >= 4); }
        if (dx1 == 2) { validA = validA && (wA < WW - 4); validB = validB && (wB < WW - 4); }
        if (dy1 == 0) { validA = validA && (h >= 4);      validB = validB && (h >= 4); }
        if (dy1 == 2) { validA = validA && (h < HH - 4);  validB = validB && (h < HH - 4); }

        const int ca = (CA >> (2*d)) & 3, cb = (CB >> (2*d)) & 3;
        const float dAv = (ca == 0) ? fxa0 : ((ca == 1) ? fxa1 : fxa2);
        const float dBv = (cb == 0) ? fyb0 : ((cb == 1) ? fyb1 : fyb2);
        u64 dA2, dB2;
        PACK2(dA2, dAv, dAv);
        PACK2(dB2, dBv, dBv);

        const int rowA = (byl + dy1)*18 + (bxlA + dx1);
        const float* lpA = &s_lrproj[rowA*36];
        const float* lpB = &s_lrproj[(rowA + 8)*36];
        const float* wap = &s_w0T[64*32];
        const float* wbp = &s_w0T[65*32];

        u64 accA[8], accB[8];
#pragma unroll
        for (int o = 0; o < 8; ++o) { accA[o] = 0ull; accB[o] = 0ull; }

#pragma unroll
        for (int t = 0; t < 4; ++t) {
            // ---- layer0 for k-channels t*8..t*8+7 (4 o-pairs), both pixels ----
            u64 hA2[8], hB2[8];   // dup'd activations
#pragma unroll
            for (int q = 0; q < 4; ++q) {
                const int o2 = t*8 + q*2;
                u64 l2A = *(const u64*)&lpA[o2];
                u64 l2B = *(const u64*)&lpB[o2];
                u64 wa2 = *(const u64*)&wap[o2];
                u64 wb2 = *(const u64*)&wbp[o2];
                u64 vA, vB;
                ADD2(vA, hrpA[t*4+q], l2A);
                FMA2(vA, dA2, wa2, vA);
                FMA2(vA, dB2, wb2, vA);
                ADD2(vB, hrpB[t*4+q], l2B);
                FMA2(vB, dA2, wa2, vB);
                FMA2(vB, dB2, wb2, vB);
                float x0, x1, y0, y1;
                UNPK2(x0, x1, vA);
                UNPK2(y0, y1, vB);
                x0 = fmaxf(x0, 0.01f*x0); x1 = fmaxf(x1, 0.01f*x1);
                y0 = fmaxf(y0, 0.01f*y0); y1 = fmaxf(y1, 0.01f*y1);
                PACK2(hA2[q*2+0], x0, x0);
                PACK2(hA2[q*2+1], x1, x1);
                PACK2(hB2[q*2+0], y0, y0);
                PACK2(hB2[q*2+1], y1, y1);
            }
            // ---- layer1: acc[o-pair] += w1T[k][o-pair] * dup(h0[k]) ----
#pragma unroll
            for (int kk = 0; kk < 8; ++kk) {
                const int k = t*8 + kk;
                const ulonglong2* wr = (const ulonglong2*)&s_w1T[k*16];
                ulonglong2 q0 = wr[0], q1 = wr[1], q2 = wr[2], q3 = wr[3];
                FMA2(accA[0], q0.x, hA2[kk], accA[0]);
                FMA2(accA[1], q0.y, hA2[kk], accA[1]);
                FMA2(accA[2], q1.x, hA2[kk], accA[2]);
                FMA2(accA[3], q1.y, hA2[kk], accA[3]);
                FMA2(accA[4], q2.x, hA2[kk], accA[4]);
                FMA2(accA[5], q2.y, hA2[kk], accA[5]);
                FMA2(accA[6], q3.x, hA2[kk], accA[6]);
                FMA2(accA[7], q3.y, hA2[kk], accA[7]);
                FMA2(accB[0], q0.x, hB2[kk], accB[0]);
                FMA2(accB[1], q0.y, hB2[kk], accB[1]);
                FMA2(accB[2], q1.x, hB2[kk], accB[2]);
                FMA2(accB[3], q1.y, hB2[kk], accB[3]);
                FMA2(accB[4], q2.x, hB2[kk], accB[4]);
                FMA2(accB[5], q2.y, hB2[kk], accB[5]);
                FMA2(accB[6], q3.x, hB2[kk], accB[6]);
                FMA2(accB[7], q3.y, hB2[kk], accB[7]);
            }
        }

        // ---- layer1 lrelu -> dup'd scalars for layer2 ----
        u64 g1A[16], g1B[16];
#pragma unroll
        for (int o = 0; o < 8; ++o) {
            float x0, x1, y0, y1;
            UNPK2(x0, x1, accA[o]);
            UNPK2(y0, y1, accB[o]);
            x0 = fmaxf(x0, 0.01f*x0); x1 = fmaxf(x1, 0.01f*x1);
            y0 = fmaxf(y0, 0.01f*y0); y1 = fmaxf(y1, 0.01f*y1);
            PACK2(g1A[o*2+0], x0, x0);
            PACK2(g1A[o*2+1], x1, x1);
            PACK2(g1B[o*2+0], y0, y0);
            PACK2(g1B[o*2+1], y1, y1);
        }

        // ---- layer2: 4 o-pairs, k = 0..15 ----
        u64 c2A[4], c2B[4];
#pragma unroll
        for (int o = 0; o < 4; ++o) { c2A[o] = 0ull; c2B[o] = 0ull; }
#pragma unroll
        for (int k = 0; k < 16; ++k) {
            const ulonglong2* wr = (const ulonglong2*)&s_w2T[k*8];
            ulonglong2 q0 = wr[0], q1 = wr[1];
            FMA2(c2A[0], q0.x, g1A[k], c2A[0]);
            FMA2(c2A[1], q0.y, g1A[k], c2A[1]);
            FMA2(c2A[2], q1.x, g1A[k], c2A[2]);
            FMA2(c2A[3], q1.y, g1A[k], c2A[3]);
            FMA2(c2B[0], q0.x, g1B[k], c2B[0]);
            FMA2(c2B[1], q0.y, g1B[k], c2B[1]);
            FMA2(c2B[2], q1.x, g1B[k], c2B[2]);
            FMA2(c2B[3], q1.y, g1B[k], c2B[3]);
        }

        // ---- layer2 lrelu + layer3 dot (scalar) ----
        float aA = 0.f, aB = 0.f;
#pragma unroll
        for (int o = 0; o < 4; ++o) {
            float x0, x1, y0, y1;
            UNPK2(x0, x1, c2A[o]);
            UNPK2(y0, y1, c2B[o]);
            x0 = fmaxf(x0, 0.01f*x0); x1 = fmaxf(x1, 0.01f*x1);
            y0 = fmaxf(y0, 0.01f*y0); y1 = fmaxf(y1, 0.01f*y1);
            aA = fmaf(w3r[o*2+0], x0, aA);
            aA = fmaf(w3r[o*2+1], x1, aA);
            aB = fmaf(w3r[o*2+0], y0, aB);
            aB = fmaf(w3r[o*2+1], y1, aB);
        }
        s_logit[tid*9 + d]        = validA ? aA : -100.0f;
        s_logit[(tid+256)*9 + d]  = validB ? aB : -100.0f;
    }

    // ---------------- softmax over the 9 directions, both pixels ----------------
#pragma unroll 1
    for (int pp = 0; pp < 2; ++pp) {
        const int pid = tid + pp*256;
        float lv[9];
#pragma unroll
        for (int d = 0; d < 9; ++d) lv[d] = s_logit[pid*9 + d];
        float m = lv[0];
#pragma unroll
        for (int d = 1; d < 9; ++d) m = fmaxf(m, lv[d]);
        float ssum = 0.f;
#pragma unroll
        for (int d = 0; d < 9; ++d) { float e = __expf(lv[d] - m); ssum += e; lv[d] = e; }
        const float inv = 1.0f / ssum;
        float* op = out + (size_t)b*9*HWs + (size_t)h*WW + wA + pp*32;
#pragma unroll
        for (int d = 0; d < 9; ++d) op[(size_t)d*HWs] = lv[d] * inv;
    }
}

extern "C" void kernel_launch(void* const* d_in, const int* in_sizes, int n_in,
                              void* d_out, int out_size) {
    const float* lr = (const float*)d_in[0];
    const float* hr = (const float*)d_in[1];
    // d_in[2], d_in[3] (lr_feature_r / hr_feature_r) are unused by the reference.
    const float* w0 = (const float*)d_in[4];
    const float* w1 = (const float*)d_in[5];
    const float* w2 = (const float*)d_in[6];
    const float* w3 = (const float*)d_in[7];
    dim3 grid(WW/64, HH/8, BB);
    erc_kernel<<<grid, 256>>>(lr, hr, w0, w1, w2, w3, (float*)d_out);
}